// round 2
// baseline (speedup 1.0000x reference)
#include <cuda_runtime.h>
#include <math.h>

#define BB   8
#define DD   512
#define NHH  8
#define HDD  64
#define HH   2048
#define NLL  2
#define VV   32000
#define SMAX 64
#define EPSL 1e-5f

// ---------------- device scratch (no allocations allowed) ----------------
__device__ float g_pe[SMAX * DD];
__device__ float g_x[BB * DD];      // current hidden (layer input / final)
__device__ float g_x2[BB * DD];     // post-LN2 hidden (residual for LN3)
__device__ float g_q[BB * DD];
__device__ float g_att[BB * DD];
__device__ float g_proj[BB * DD];
__device__ float g_hbuf[BB * HH];
__device__ float g_f2[BB * DD];
__device__ float g_kc[NLL * BB * NHH * SMAX * HDD];
__device__ float g_vc[NLL * BB * NHH * SMAX * HDD];
__device__ float g_cavec[NLL * BB * DD];
__device__ int   g_tok[BB * SMAX];
__device__ unsigned long long g_amax[BB];

// ---------------- helpers ----------------
__device__ __forceinline__ float wred(float v) {
    v += __shfl_xor_sync(0xffffffffu, v, 16);
    v += __shfl_xor_sync(0xffffffffu, v, 8);
    v += __shfl_xor_sync(0xffffffffu, v, 4);
    v += __shfl_xor_sync(0xffffffffu, v, 2);
    v += __shfl_xor_sync(0xffffffffu, v, 1);
    return v;
}

// block-wide sum over 256 threads; result broadcast to all threads
__device__ __forceinline__ float blocksum(float v, float* red) {
    int tid = threadIdx.x;
    __syncthreads();           // protect prior use of red
    red[tid] = v;
    __syncthreads();
    for (int s = 128; s > 0; s >>= 1) {
        if (tid < s) red[tid] += red[tid + s];
        __syncthreads();
    }
    return red[0];
}

// ---------------- precompute ----------------
__global__ void k_pe() {
    int pos = blockIdx.x;          // SMAX blocks
    int d   = threadIdx.x;         // DD threads
    double div = exp((double)(d & ~1) * (-9.210340371976184 / (double)DD)); // ln(10000)
    float arg = (float)pos * (float)div;
    g_pe[pos * DD + d] = (d & 1) ? cosf(arg) : sinf(arg);
    if (pos == 0) {                // d in [0,512) covers BB*SMAX = 512 token slots
        g_tok[d] = ((d & (SMAX - 1)) == 0) ? 1 : 0;   // SOS = 1 at position 0
    }
}

// cross-attention collapses to a per-(layer,batch) constant vector
__global__ void k_cavec(const float* __restrict__ mem,
                        const float* __restrict__ ca_in_w,
                        const float* __restrict__ ca_in_b,
                        const float* __restrict__ ca_out_w,
                        const float* __restrict__ ca_out_b) {
    __shared__ float vmem[DD];
    int l = blockIdx.x / BB, b = blockIdx.x % BB;
    const float* m = mem + b * DD;
    for (int j = threadIdx.x; j < DD; j += blockDim.x) {
        const float* w = ca_in_w + ((size_t)l * 3 * DD + 2 * DD + j) * DD;
        float acc = ca_in_b[l * 3 * DD + 2 * DD + j];
        for (int d = 0; d < DD; d++) acc += m[d] * w[d];
        vmem[j] = acc;
    }
    __syncthreads();
    for (int dd = threadIdx.x; dd < DD; dd += blockDim.x) {
        const float* w = ca_out_w + ((size_t)l * DD + dd) * DD;
        float acc = ca_out_b[l * DD + dd];
        for (int j = 0; j < DD; j++) acc += vmem[j] * w[j];
        g_cavec[(l * BB + b) * DD + dd] = acc;
    }
}

// ---------------- per-step kernels ----------------

// QKV projection for position t (layer l). For l==0 the embedding+PE is
// computed on the fly per warp; block 0 additionally materializes g_x.
__global__ void k_qkv(const float* __restrict__ emb,
                      const float* __restrict__ w_in,
                      const float* __restrict__ b_in,
                      int l, int t) {
    int lane = threadIdx.x & 31;
    int warp = threadIdx.x >> 5;

    if (l == 0 && blockIdx.x == 0) {
        for (int i = threadIdx.x; i < BB * DD; i += blockDim.x) {
            int b = i >> 9, d = i & 511;
            int tok = g_tok[b * SMAX + t];
            g_x[i] = emb[(size_t)tok * DD + d] + g_pe[t * DD + d];
        }
    }

    int gw = blockIdx.x * 8 + warp;                 // 96 blocks * 8 warps
    for (int o = gw; o < BB * 3 * DD; o += 96 * 8) {
        int b = o / (3 * DD), j = o % (3 * DD);
        const float4* w4 = (const float4*)(w_in + ((size_t)l * 3 * DD + j) * DD);
        float acc = 0.f;
        if (l == 0) {
            int tok = g_tok[b * SMAX + t];
            const float4* e4 = (const float4*)(emb + (size_t)tok * DD);
            const float4* p4 = (const float4*)(g_pe + t * DD);
            #pragma unroll
            for (int k2 = 0; k2 < 4; k2++) {
                int i4 = lane + k2 * 32;
                float4 w = w4[i4]; float4 e = e4[i4]; float4 p = p4[i4];
                acc += w.x * (e.x + p.x) + w.y * (e.y + p.y)
                     + w.z * (e.z + p.z) + w.w * (e.w + p.w);
            }
        } else {
            const float4* x4 = (const float4*)(g_x + b * DD);
            #pragma unroll
            for (int k2 = 0; k2 < 4; k2++) {
                int i4 = lane + k2 * 32;
                float4 w = w4[i4]; float4 x = x4[i4];
                acc += w.x * x.x + w.y * x.y + w.z * x.z + w.w * x.w;
            }
        }
        acc = wred(acc);
        if (lane == 0) {
            acc += b_in[l * 3 * DD + j];
            if (j < DD) {
                g_q[b * DD + j] = acc;
            } else if (j < 2 * DD) {
                int h = (j - DD) >> 6, d = (j - DD) & 63;
                g_kc[(((l * BB + b) * NHH + h) * SMAX + t) * HDD + d] = acc;
            } else {
                int h = (j - 2 * DD) >> 6, d = (j - 2 * DD) & 63;
                g_vc[(((l * BB + b) * NHH + h) * SMAX + t) * HDD + d] = acc;
            }
        }
    }
}

// causal self-attention for position t: one block per batch, one warp per head
__global__ void k_attn(int l, int t) {
    __shared__ float sp[NHH][SMAX];
    int b = blockIdx.x;
    int h = threadIdx.x >> 5, lane = threadIdx.x & 31;
    int n = t + 1;
    const float* qp    = g_q + b * DD + h * HDD;
    const float* kbase = g_kc + (size_t)(((l * BB + b) * NHH + h) * SMAX) * HDD;
    const float* vbase = g_vc + (size_t)(((l * BB + b) * NHH + h) * SMAX) * HDD;

    float s0 = -1e30f, s1 = -1e30f;
    const float4* q4 = (const float4*)qp;
    if (lane < n) {
        const float4* k4 = (const float4*)(kbase + (size_t)lane * HDD);
        float a = 0.f;
        #pragma unroll
        for (int k2 = 0; k2 < 16; k2++) {
            float4 kk = k4[k2], qq = q4[k2];
            a += kk.x * qq.x + kk.y * qq.y + kk.z * qq.z + kk.w * qq.w;
        }
        s0 = a * 0.125f;   // 1/sqrt(64)
    }
    if (lane + 32 < n) {
        const float4* k4 = (const float4*)(kbase + (size_t)(lane + 32) * HDD);
        float a = 0.f;
        #pragma unroll
        for (int k2 = 0; k2 < 16; k2++) {
            float4 kk = k4[k2], qq = q4[k2];
            a += kk.x * qq.x + kk.y * qq.y + kk.z * qq.z + kk.w * qq.w;
        }
        s1 = a * 0.125f;
    }
    float m = fmaxf(s0, s1);
    for (int off = 16; off; off >>= 1) m = fmaxf(m, __shfl_xor_sync(0xffffffffu, m, off));
    float p0 = (lane < n)      ? expf(s0 - m) : 0.f;
    float p1 = (lane + 32 < n) ? expf(s1 - m) : 0.f;
    float sum = wred(p0 + p1);
    sp[h][lane]      = p0;
    sp[h][lane + 32] = p1;
    __syncwarp();
    float o0 = 0.f, o1 = 0.f;
    for (int j = 0; j < n; j++) {
        float p = sp[h][j];
        o0 += p * vbase[(size_t)j * HDD + lane];
        o1 += p * vbase[(size_t)j * HDD + lane + 32];
    }
    float inv = 1.f / sum;
    g_att[b * DD + h * HDD + lane]      = o0 * inv;
    g_att[b * DD + h * HDD + lane + 32] = o1 * inv;
}

// self-attention output projection (grid-wide GEMV batch)
__global__ void k_proj(const float* __restrict__ w,
                       const float* __restrict__ bias, int l) {
    int lane = threadIdx.x & 31;
    int gw = blockIdx.x * 8 + (threadIdx.x >> 5);    // 64 blocks -> 512 warps
    for (int o = gw; o < BB * DD; o += 512) {
        int b = o >> 9, dd = o & 511;
        const float4* w4 = (const float4*)(w + ((size_t)l * DD + dd) * DD);
        const float4* a4 = (const float4*)(g_att + b * DD);
        float acc = 0.f;
        #pragma unroll
        for (int k2 = 0; k2 < 4; k2++) {
            int i4 = lane + k2 * 32;
            float4 ww = w4[i4], aa = a4[i4];
            acc += ww.x * aa.x + ww.y * aa.y + ww.z * aa.z + ww.w * aa.w;
        }
        acc = wred(acc);
        if (lane == 0) g_proj[o] = acc + bias[l * DD + dd];
    }
}

// fused: LN1(x + proj) -> +ca_vec -> LN2 -> (store g_x2) -> FFN1+relu chunk
// grid = (b, chunk): 8*8 = 64 blocks, 256 threads
__global__ void k_ffn1(const float* __restrict__ w1,
                       const float* __restrict__ b1,
                       const float* __restrict__ g1, const float* __restrict__ be1,
                       const float* __restrict__ g2, const float* __restrict__ be2,
                       int l) {
    __shared__ float xln[DD];
    __shared__ float red[256];
    int b = blockIdx.x >> 3;
    int chunk = blockIdx.x & 7;
    int tid = threadIdx.x;

    float y0 = g_x[b * DD + tid]       + g_proj[b * DD + tid];
    float y1 = g_x[b * DD + tid + 256] + g_proj[b * DD + tid + 256];
    float m1 = blocksum(y0 + y1, red) * (1.f / DD);
    float d0 = y0 - m1, d1 = y1 - m1;
    float v1 = blocksum(d0 * d0 + d1 * d1, red) * (1.f / DD);
    float r1 = 1.f / sqrtf(v1 + EPSL);
    float z0 = d0 * r1 * g1[l * DD + tid]       + be1[l * DD + tid]
             + g_cavec[(l * BB + b) * DD + tid];
    float z1 = d1 * r1 * g1[l * DD + tid + 256] + be1[l * DD + tid + 256]
             + g_cavec[(l * BB + b) * DD + tid + 256];
    float m2 = blocksum(z0 + z1, red) * (1.f / DD);
    float e0 = z0 - m2, e1 = z1 - m2;
    float v2 = blocksum(e0 * e0 + e1 * e1, red) * (1.f / DD);
    float r2 = 1.f / sqrtf(v2 + EPSL);
    float x0 = e0 * r2 * g2[l * DD + tid]       + be2[l * DD + tid];
    float x1 = e1 * r2 * g2[l * DD + tid + 256] + be2[l * DD + tid + 256];
    xln[tid] = x0;
    xln[tid + 256] = x1;
    if (chunk == 0) {
        g_x2[b * DD + tid] = x0;
        g_x2[b * DD + tid + 256] = x1;
    }
    __syncthreads();

    int lane = tid & 31, warp = tid >> 5;
    for (int oo = warp; oo < 256; oo += 8) {
        int hh = chunk * 256 + oo;
        const float4* w4 = (const float4*)(w1 + ((size_t)l * HH + hh) * DD);
        const float4* x4 = (const float4*)xln;
        float acc = 0.f;
        #pragma unroll
        for (int k2 = 0; k2 < 4; k2++) {
            int i4 = lane + k2 * 32;
            float4 ww = w4[i4], xx = x4[i4];
            acc += ww.x * xx.x + ww.y * xx.y + ww.z * xx.z + ww.w * xx.w;
        }
        acc = wred(acc);
        if (lane == 0) g_hbuf[b * HH + hh] = fmaxf(acc + b1[l * HH + hh], 0.f);
    }
}

__global__ void k_ffn2(const float* __restrict__ w2,
                       const float* __restrict__ b2, int l) {
    int lane = threadIdx.x & 31;
    int gw = blockIdx.x * 8 + (threadIdx.x >> 5);    // 64 blocks -> 512 warps
    for (int o = gw; o < BB * DD; o += 512) {
        int b = o >> 9, dd = o & 511;
        const float4* w4 = (const float4*)(w2 + ((size_t)l * DD + dd) * HH);
        const float4* h4 = (const float4*)(g_hbuf + b * HH);
        float acc = 0.f;
        #pragma unroll
        for (int k2 = 0; k2 < 16; k2++) {
            int i4 = lane + k2 * 32;
            float4 ww = w4[i4], hh = h4[i4];
            acc += ww.x * hh.x + ww.y * hh.y + ww.z * hh.z + ww.w * hh.w;
        }
        acc = wred(acc);
        if (lane == 0) g_f2[o] = acc + b2[l * DD + dd];
    }
}

__global__ void k_ln3(const float* __restrict__ g3,
                      const float* __restrict__ be3, int l) {
    __shared__ float red[256];
    int b = blockIdx.x, tid = threadIdx.x;
    float y0 = g_x2[b * DD + tid]       + g_f2[b * DD + tid];
    float y1 = g_x2[b * DD + tid + 256] + g_f2[b * DD + tid + 256];
    float m = blocksum(y0 + y1, red) * (1.f / DD);
    float d0 = y0 - m, d1 = y1 - m;
    float v = blocksum(d0 * d0 + d1 * d1, red) * (1.f / DD);
    float r = 1.f / sqrtf(v + EPSL);
    g_x[b * DD + tid]       = d0 * r * g3[l * DD + tid]       + be3[l * DD + tid];
    g_x[b * DD + tid + 256] = d1 * r * g3[l * DD + tid + 256] + be3[l * DD + tid + 256];
    if (l == 1 && tid < BB && b == 0) g_amax[tid] = 0ull;   // reset argmax slots
}

// logits GEMV batch + fused argmax (first-index tie-break via key encoding)
__global__ void k_logits(const float* __restrict__ ow,
                         const float* __restrict__ ob,
                         float* __restrict__ out_logits, int t, int L) {
    __shared__ float hs[BB * DD];
    for (int i = threadIdx.x; i < BB * DD; i += blockDim.x) hs[i] = g_x[i];
    __syncthreads();
    int lane = threadIdx.x & 31;
    int gw = blockIdx.x * 8 + (threadIdx.x >> 5);    // 148 blocks -> 1184 warps
    for (int v = gw; v < VV; v += 1184) {
        const float4* w4 = (const float4*)(ow + (size_t)v * DD);
        float4 wr[4];
        #pragma unroll
        for (int k2 = 0; k2 < 4; k2++) wr[k2] = w4[lane + k2 * 32];
        float acc[BB];
        #pragma unroll
        for (int b = 0; b < BB; b++) {
            const float4* h4 = (const float4*)(hs + b * DD);
            float a = 0.f;
            #pragma unroll
            for (int k2 = 0; k2 < 4; k2++) {
                float4 hh = h4[lane + k2 * 32];
                a += wr[k2].x * hh.x + wr[k2].y * hh.y
                   + wr[k2].z * hh.z + wr[k2].w * hh.w;
            }
            acc[b] = a;
        }
        #pragma unroll
        for (int off = 16; off; off >>= 1) {
            #pragma unroll
            for (int b = 0; b < BB; b++)
                acc[b] += __shfl_xor_sync(0xffffffffu, acc[b], off);
        }
        if (lane < BB) {
            float val = acc[lane] + ob[v];
            out_logits[((size_t)lane * L + t) * VV + v] = val;
            unsigned u = __float_as_uint(val);
            u = (u & 0x80000000u) ? ~u : (u | 0x80000000u);
            unsigned long long key =
                ((unsigned long long)u << 32) | (unsigned)(0xFFFFFFFFu - (unsigned)v);
            atomicMax(&g_amax[lane], key);
        }
    }
}

__global__ void k_next(float* __restrict__ out_tok, int t, int L, int wt) {
    int b = threadIdx.x;
    if (b < BB) {
        unsigned long long key = g_amax[b];
        int idx = (int)(0xFFFFFFFFu - (unsigned)(key & 0xFFFFFFFFull));
        g_tok[b * SMAX + t + 1] = idx;
        if (wt) out_tok[b * L + t] = (float)idx;
    }
}

// ---------------- host ----------------
extern "C" void kernel_launch(void* const* d_in, const int* in_sizes, int n_in,
                              void* d_out, int out_size) {
    (void)in_sizes; (void)n_in;
    const float* memory    = (const float*)d_in[0];
    const float* embedding = (const float*)d_in[1];
    const float* sa_in_w   = (const float*)d_in[2];
    const float* sa_in_b   = (const float*)d_in[3];
    const float* sa_out_w  = (const float*)d_in[4];
    const float* sa_out_b  = (const float*)d_in[5];
    const float* ca_in_w   = (const float*)d_in[6];
    const float* ca_in_b   = (const float*)d_in[7];
    const float* ca_out_w  = (const float*)d_in[8];
    const float* ca_out_b  = (const float*)d_in[9];
    const float* ff1_w     = (const float*)d_in[10];
    const float* ff1_b     = (const float*)d_in[11];
    const float* ff2_w     = (const float*)d_in[12];
    const float* ff2_b     = (const float*)d_in[13];
    const float* ln1_g     = (const float*)d_in[14];
    const float* ln1_b     = (const float*)d_in[15];
    const float* ln2_g     = (const float*)d_in[16];
    const float* ln2_b     = (const float*)d_in[17];
    const float* ln3_g     = (const float*)d_in[18];
    const float* ln3_b     = (const float*)d_in[19];
    const float* out_w     = (const float*)d_in[20];
    const float* out_b     = (const float*)d_in[21];

    // Derive L and output layout from out_size:
    //   tokens(B*L) + logits(B*L*V) concatenated, or logits only.
    int L, with_tok;
    if (out_size % (BB * (VV + 1)) == 0) { L = out_size / (BB * (VV + 1)); with_tok = 1; }
    else if (out_size % (BB * VV) == 0)  { L = out_size / (BB * VV);       with_tok = 0; }
    else                                 { L = 48;                         with_tok = 1; }
    if (L > SMAX - 1) L = SMAX - 1;
    if (L <= 0) return;

    float* out_f   = (float*)d_out;
    float* tok_out = out_f;
    float* log_out = with_tok ? (out_f + (size_t)BB * L) : out_f;

    k_pe<<<SMAX, DD>>>();
    k_cavec<<<NLL * BB, 256>>>(memory, ca_in_w, ca_in_b, ca_out_w, ca_out_b);

    for (int t = 0; t < L; t++) {
        for (int l = 0; l < NLL; l++) {
            k_qkv <<<96, 256>>>(embedding, sa_in_w, sa_in_b, l, t);
            k_attn<<<BB, 256>>>(l, t);
            k_proj<<<64, 256>>>(sa_out_w, sa_out_b, l);
            k_ffn1<<<64, 256>>>(ff1_w, ff1_b, ln1_g, ln1_b, ln2_g, ln2_b, l);
            k_ffn2<<<64, 256>>>(ff2_w, ff2_b, l);
            k_ln3 <<<BB, 256>>>(ln3_g, ln3_b, l);
        }
        k_logits<<<148, 256>>>(out_w, out_b, log_out, t, L);
        k_next  <<<1, 32>>>(tok_out, t, L, with_tok);
    }
}

// round 4
// speedup vs baseline: 1.0096x; 1.0096x over previous
#include <cuda_runtime.h>
#include <math.h>

#define BB   8
#define DD   512
#define NHH  8
#define HDD  64
#define HH   2048
#define NLL  2
#define VV   32000
#define SMAX 64
#define EPSL 1e-5f

// ---------------- device scratch (no allocations allowed) ----------------
__device__ float g_pe[SMAX * DD];
__device__ float g_x[BB * DD];      // current hidden (layer input / final)
__device__ float g_x2[BB * DD];     // post-LN2 hidden (residual for LN3)
__device__ float g_q[BB * DD];
__device__ float g_att[BB * DD];
__device__ float g_proj[BB * DD];
__device__ float g_hbuf[BB * HH];
__device__ float g_f2[BB * DD];
__device__ float g_kc[NLL * BB * NHH * SMAX * HDD];
__device__ float g_vc[NLL * BB * NHH * SMAX * HDD];
__device__ float g_cavec[NLL * BB * DD];
__device__ int   g_tok[BB * SMAX];
__device__ unsigned long long g_amax[BB];

// ---------------- helpers ----------------
__device__ __forceinline__ float wred(float v) {
    v += __shfl_xor_sync(0xffffffffu, v, 16);
    v += __shfl_xor_sync(0xffffffffu, v, 8);
    v += __shfl_xor_sync(0xffffffffu, v, 4);
    v += __shfl_xor_sync(0xffffffffu, v, 2);
    v += __shfl_xor_sync(0xffffffffu, v, 1);
    return v;
}

// block-wide sum over 256 threads; result broadcast to all threads
__device__ __forceinline__ float blocksum(float v, float* red) {
    int tid = threadIdx.x;
    __syncthreads();           // protect prior use of red
    red[tid] = v;
    __syncthreads();
    for (int s = 128; s > 0; s >>= 1) {
        if (tid < s) red[tid] += red[tid + s];
        __syncthreads();
    }
    return red[0];
}

// ---------------- precompute ----------------
__global__ void k_pe() {
    int pos = blockIdx.x;          // SMAX blocks
    int d   = threadIdx.x;         // DD threads
    double div = exp((double)(d & ~1) * (-9.210340371976184 / (double)DD)); // ln(10000)
    float arg = (float)pos * (float)div;
    g_pe[pos * DD + d] = (d & 1) ? cosf(arg) : sinf(arg);
    if (pos == 0) {                // d in [0,512) covers BB*SMAX = 512 token slots
        g_tok[d] = ((d & (SMAX - 1)) == 0) ? 1 : 0;   // SOS = 1 at position 0
    }
}

// cross-attention collapses to a per-(layer,batch) constant vector
__global__ void k_cavec(const float* __restrict__ mem,
                        const float* __restrict__ ca_in_w,
                        const float* __restrict__ ca_in_b,
                        const float* __restrict__ ca_out_w,
                        const float* __restrict__ ca_out_b) {
    __shared__ float vmem[DD];
    int l = blockIdx.x / BB, b = blockIdx.x % BB;
    const float* m = mem + b * DD;
    for (int j = threadIdx.x; j < DD; j += blockDim.x) {
        const float* w = ca_in_w + ((size_t)l * 3 * DD + 2 * DD + j) * DD;
        float acc = ca_in_b[l * 3 * DD + 2 * DD + j];
        for (int d = 0; d < DD; d++) acc += m[d] * w[d];
        vmem[j] = acc;
    }
    __syncthreads();
    for (int dd = threadIdx.x; dd < DD; dd += blockDim.x) {
        const float* w = ca_out_w + ((size_t)l * DD + dd) * DD;
        float acc = ca_out_b[l * DD + dd];
        for (int j = 0; j < DD; j++) acc += vmem[j] * w[j];
        g_cavec[(l * BB + b) * DD + dd] = acc;
    }
}

// ---------------- per-step kernels ----------------

// QKV projection for position t (layer l). For l==0 the embedding+PE is
// computed on the fly per warp; block 0 additionally materializes g_x.
__global__ void k_qkv(const float* __restrict__ emb,
                      const float* __restrict__ w_in,
                      const float* __restrict__ b_in,
                      int l, int t) {
    int lane = threadIdx.x & 31;
    int warp = threadIdx.x >> 5;

    if (l == 0 && blockIdx.x == 0) {
        for (int i = threadIdx.x; i < BB * DD; i += blockDim.x) {
            int b = i >> 9, d = i & 511;
            int tok = g_tok[b * SMAX + t];
            g_x[i] = emb[(size_t)tok * DD + d] + g_pe[t * DD + d];
        }
    }

    int gw = blockIdx.x * 8 + warp;                 // 96 blocks * 8 warps
    for (int o = gw; o < BB * 3 * DD; o += 96 * 8) {
        int b = o / (3 * DD), j = o % (3 * DD);
        const float4* w4 = (const float4*)(w_in + ((size_t)l * 3 * DD + j) * DD);
        float acc = 0.f;
        if (l == 0) {
            int tok = g_tok[b * SMAX + t];
            const float4* e4 = (const float4*)(emb + (size_t)tok * DD);
            const float4* p4 = (const float4*)(g_pe + t * DD);
            #pragma unroll
            for (int k2 = 0; k2 < 4; k2++) {
                int i4 = lane + k2 * 32;
                float4 w = w4[i4]; float4 e = e4[i4]; float4 p = p4[i4];
                acc += w.x * (e.x + p.x) + w.y * (e.y + p.y)
                     + w.z * (e.z + p.z) + w.w * (e.w + p.w);
            }
        } else {
            const float4* x4 = (const float4*)(g_x + b * DD);
            #pragma unroll
            for (int k2 = 0; k2 < 4; k2++) {
                int i4 = lane + k2 * 32;
                float4 w = w4[i4]; float4 x = x4[i4];
                acc += w.x * x.x + w.y * x.y + w.z * x.z + w.w * x.w;
            }
        }
        acc = wred(acc);
        if (lane == 0) {
            acc += b_in[l * 3 * DD + j];
            if (j < DD) {
                g_q[b * DD + j] = acc;
            } else if (j < 2 * DD) {
                int h = (j - DD) >> 6, d = (j - DD) & 63;
                g_kc[(((l * BB + b) * NHH + h) * SMAX + t) * HDD + d] = acc;
            } else {
                int h = (j - 2 * DD) >> 6, d = (j - 2 * DD) & 63;
                g_vc[(((l * BB + b) * NHH + h) * SMAX + t) * HDD + d] = acc;
            }
        }
    }
}

// causal self-attention for position t: one block per batch, one warp per head
__global__ void k_attn(int l, int t) {
    __shared__ float sp[NHH][SMAX];
    int b = blockIdx.x;
    int h = threadIdx.x >> 5, lane = threadIdx.x & 31;
    int n = t + 1;
    const float* qp    = g_q + b * DD + h * HDD;
    const float* kbase = g_kc + (size_t)(((l * BB + b) * NHH + h) * SMAX) * HDD;
    const float* vbase = g_vc + (size_t)(((l * BB + b) * NHH + h) * SMAX) * HDD;

    float s0 = -1e30f, s1 = -1e30f;
    const float4* q4 = (const float4*)qp;
    if (lane < n) {
        const float4* k4 = (const float4*)(kbase + (size_t)lane * HDD);
        float a = 0.f;
        #pragma unroll
        for (int k2 = 0; k2 < 16; k2++) {
            float4 kk = k4[k2], qq = q4[k2];
            a += kk.x * qq.x + kk.y * qq.y + kk.z * qq.z + kk.w * qq.w;
        }
        s0 = a * 0.125f;   // 1/sqrt(64)
    }
    if (lane + 32 < n) {
        const float4* k4 = (const float4*)(kbase + (size_t)(lane + 32) * HDD);
        float a = 0.f;
        #pragma unroll
        for (int k2 = 0; k2 < 16; k2++) {
            float4 kk = k4[k2], qq = q4[k2];
            a += kk.x * qq.x + kk.y * qq.y + kk.z * qq.z + kk.w * qq.w;
        }
        s1 = a * 0.125f;
    }
    float m = fmaxf(s0, s1);
    for (int off = 16; off; off >>= 1) m = fmaxf(m, __shfl_xor_sync(0xffffffffu, m, off));
    float p0 = (lane < n)      ? expf(s0 - m) : 0.f;
    float p1 = (lane + 32 < n) ? expf(s1 - m) : 0.f;
    float sum = wred(p0 + p1);
    sp[h][lane]      = p0;
    sp[h][lane + 32] = p1;
    __syncwarp();
    float o0 = 0.f, o1 = 0.f;
    for (int j = 0; j < n; j++) {
        float p = sp[h][j];
        o0 += p * vbase[(size_t)j * HDD + lane];
        o1 += p * vbase[(size_t)j * HDD + lane + 32];
    }
    float inv = 1.f / sum;
    g_att[b * DD + h * HDD + lane]      = o0 * inv;
    g_att[b * DD + h * HDD + lane + 32] = o1 * inv;
}

// self-attention output projection (grid-wide GEMV batch)
__global__ void k_proj(const float* __restrict__ w,
                       const float* __restrict__ bias, int l) {
    int lane = threadIdx.x & 31;
    int gw = blockIdx.x * 8 + (threadIdx.x >> 5);    // 64 blocks -> 512 warps
    for (int o = gw; o < BB * DD; o += 512) {
        int b = o >> 9, dd = o & 511;
        const float4* w4 = (const float4*)(w + ((size_t)l * DD + dd) * DD);
        const float4* a4 = (const float4*)(g_att + b * DD);
        float acc = 0.f;
        #pragma unroll
        for (int k2 = 0; k2 < 4; k2++) {
            int i4 = lane + k2 * 32;
            float4 ww = w4[i4], aa = a4[i4];
            acc += ww.x * aa.x + ww.y * aa.y + ww.z * aa.z + ww.w * aa.w;
        }
        acc = wred(acc);
        if (lane == 0) g_proj[o] = acc + bias[l * DD + dd];
    }
}

// fused: LN1(x + proj) -> +ca_vec -> LN2 -> (store g_x2) -> FFN1+relu chunk
// grid = (b, chunk): 8*8 = 64 blocks, 256 threads
__global__ void k_ffn1(const float* __restrict__ w1,
                       const float* __restrict__ b1,
                       const float* __restrict__ g1, const float* __restrict__ be1,
                       const float* __restrict__ g2, const float* __restrict__ be2,
                       int l) {
    __shared__ float xln[DD];
    __shared__ float red[256];
    int b = blockIdx.x >> 3;
    int chunk = blockIdx.x & 7;
    int tid = threadIdx.x;

    float y0 = g_x[b * DD + tid]       + g_proj[b * DD + tid];
    float y1 = g_x[b * DD + tid + 256] + g_proj[b * DD + tid + 256];
    float m1 = blocksum(y0 + y1, red) * (1.f / DD);
    float d0 = y0 - m1, d1 = y1 - m1;
    float v1 = blocksum(d0 * d0 + d1 * d1, red) * (1.f / DD);
    float r1 = 1.f / sqrtf(v1 + EPSL);
    float z0 = d0 * r1 * g1[l * DD + tid]       + be1[l * DD + tid]
             + g_cavec[(l * BB + b) * DD + tid];
    float z1 = d1 * r1 * g1[l * DD + tid + 256] + be1[l * DD + tid + 256]
             + g_cavec[(l * BB + b) * DD + tid + 256];
    float m2 = blocksum(z0 + z1, red) * (1.f / DD);
    float e0 = z0 - m2, e1 = z1 - m2;
    float v2 = blocksum(e0 * e0 + e1 * e1, red) * (1.f / DD);
    float r2 = 1.f / sqrtf(v2 + EPSL);
    float x0 = e0 * r2 * g2[l * DD + tid]       + be2[l * DD + tid];
    float x1 = e1 * r2 * g2[l * DD + tid + 256] + be2[l * DD + tid + 256];
    xln[tid] = x0;
    xln[tid + 256] = x1;
    if (chunk == 0) {
        g_x2[b * DD + tid] = x0;
        g_x2[b * DD + tid + 256] = x1;
    }
    __syncthreads();

    int lane = tid & 31, warp = tid >> 5;
    for (int oo = warp; oo < 256; oo += 8) {
        int hh = chunk * 256 + oo;
        const float4* w4 = (const float4*)(w1 + ((size_t)l * HH + hh) * DD);
        const float4* x4 = (const float4*)xln;
        float acc = 0.f;
        #pragma unroll
        for (int k2 = 0; k2 < 4; k2++) {
            int i4 = lane + k2 * 32;
            float4 ww = w4[i4], xx = x4[i4];
            acc += ww.x * xx.x + ww.y * xx.y + ww.z * xx.z + ww.w * xx.w;
        }
        acc = wred(acc);
        if (lane == 0) g_hbuf[b * HH + hh] = fmaxf(acc + b1[l * HH + hh], 0.f);
    }
}

__global__ void k_ffn2(const float* __restrict__ w2,
                       const float* __restrict__ b2, int l) {
    int lane = threadIdx.x & 31;
    int gw = blockIdx.x * 8 + (threadIdx.x >> 5);    // 64 blocks -> 512 warps
    for (int o = gw; o < BB * DD; o += 512) {
        int b = o >> 9, dd = o & 511;
        const float4* w4 = (const float4*)(w2 + ((size_t)l * DD + dd) * HH);
        const float4* h4 = (const float4*)(g_hbuf + b * HH);
        float acc = 0.f;
        #pragma unroll
        for (int k2 = 0; k2 < 16; k2++) {
            int i4 = lane + k2 * 32;
            float4 ww = w4[i4], hh = h4[i4];
            acc += ww.x * hh.x + ww.y * hh.y + ww.z * hh.z + ww.w * hh.w;
        }
        acc = wred(acc);
        if (lane == 0) g_f2[o] = acc + b2[l * DD + dd];
    }
}

__global__ void k_ln3(const float* __restrict__ g3,
                      const float* __restrict__ be3, int l) {
    __shared__ float red[256];
    int b = blockIdx.x, tid = threadIdx.x;
    float y0 = g_x2[b * DD + tid]       + g_f2[b * DD + tid];
    float y1 = g_x2[b * DD + tid + 256] + g_f2[b * DD + tid + 256];
    float m = blocksum(y0 + y1, red) * (1.f / DD);
    float d0 = y0 - m, d1 = y1 - m;
    float v = blocksum(d0 * d0 + d1 * d1, red) * (1.f / DD);
    float r = 1.f / sqrtf(v + EPSL);
    g_x[b * DD + tid]       = d0 * r * g3[l * DD + tid]       + be3[l * DD + tid];
    g_x[b * DD + tid + 256] = d1 * r * g3[l * DD + tid + 256] + be3[l * DD + tid + 256];
    if (l == 1 && tid < BB && b == 0) g_amax[tid] = 0ull;   // reset argmax slots
}

// logits GEMV batch + fused argmax (first-index tie-break via key encoding)
__global__ void k_logits(const float* __restrict__ ow,
                         const float* __restrict__ ob,
                         float* __restrict__ out_logits, int t, int L) {
    __shared__ float hs[BB * DD];
    for (int i = threadIdx.x; i < BB * DD; i += blockDim.x) hs[i] = g_x[i];
    __syncthreads();
    int lane = threadIdx.x & 31;
    int gw = blockIdx.x * 8 + (threadIdx.x >> 5);    // 148 blocks -> 1184 warps
    for (int v = gw; v < VV; v += 1184) {
        const float4* w4 = (const float4*)(ow + (size_t)v * DD);
        float4 wr[4];
        #pragma unroll
        for (int k2 = 0; k2 < 4; k2++) wr[k2] = w4[lane + k2 * 32];
        float acc[BB];
        #pragma unroll
        for (int b = 0; b < BB; b++) {
            const float4* h4 = (const float4*)(hs + b * DD);
            float a = 0.f;
            #pragma unroll
            for (int k2 = 0; k2 < 4; k2++) {
                float4 hh = h4[lane + k2 * 32];
                a += wr[k2].x * hh.x + wr[k2].y * hh.y
                   + wr[k2].z * hh.z + wr[k2].w * hh.w;
            }
            acc[b] = a;
        }
        #pragma unroll
        for (int off = 16; off; off >>= 1) {
            #pragma unroll
            for (int b = 0; b < BB; b++)
                acc[b] += __shfl_xor_sync(0xffffffffu, acc[b], off);
        }
        if (lane < BB) {
            float val = acc[lane] + ob[v];
            out_logits[((size_t)lane * L + t) * VV + v] = val;
            unsigned u = __float_as_uint(val);
            u = (u & 0x80000000u) ? ~u : (u | 0x80000000u);
            unsigned long long key =
                ((unsigned long long)u << 32) | (unsigned)(0xFFFFFFFFu - (unsigned)v);
            atomicMax(&g_amax[lane], key);
        }
    }
}

__global__ void k_next(float* __restrict__ out_tok, int t, int L, int wt) {
    int b = threadIdx.x;
    if (b < BB) {
        unsigned long long key = g_amax[b];
        int idx = (int)(0xFFFFFFFFu - (unsigned)(key & 0xFFFFFFFFull));
        g_tok[b * SMAX + t + 1] = idx;
        if (wt) out_tok[b * L + t] = (float)idx;
    }
}

// ---------------- host ----------------
extern "C" void kernel_launch(void* const* d_in, const int* in_sizes, int n_in,
                              void* d_out, int out_size) {
    (void)in_sizes; (void)n_in;
    const float* memory    = (const float*)d_in[0];
    const float* embedding = (const float*)d_in[1];
    const float* sa_in_w   = (const float*)d_in[2];
    const float* sa_in_b   = (const float*)d_in[3];
    const float* sa_out_w  = (const float*)d_in[4];
    const float* sa_out_b  = (const float*)d_in[5];
    const float* ca_in_w   = (const float*)d_in[6];
    const float* ca_in_b   = (const float*)d_in[7];
    const float* ca_out_w  = (const float*)d_in[8];
    const float* ca_out_b  = (const float*)d_in[9];
    const float* ff1_w     = (const float*)d_in[10];
    const float* ff1_b     = (const float*)d_in[11];
    const float* ff2_w     = (const float*)d_in[12];
    const float* ff2_b     = (const float*)d_in[13];
    const float* ln1_g     = (const float*)d_in[14];
    const float* ln1_b     = (const float*)d_in[15];
    const float* ln2_g     = (const float*)d_in[16];
    const float* ln2_b     = (const float*)d_in[17];
    const float* ln3_g     = (const float*)d_in[18];
    const float* ln3_b     = (const float*)d_in[19];
    const float* out_w     = (const float*)d_in[20];
    const float* out_b     = (const float*)d_in[21];

    // Derive L and output layout from out_size:
    //   tokens(B*L) + logits(B*L*V) concatenated, or logits only.
    int L, with_tok;
    if (out_size % (BB * (VV + 1)) == 0) { L = out_size / (BB * (VV + 1)); with_tok = 1; }
    else if (out_size % (BB * VV) == 0)  { L = out_size / (BB * VV);       with_tok = 0; }
    else                                 { L = 48;                         with_tok = 1; }
    if (L > SMAX - 1) L = SMAX - 1;
    if (L <= 0) return;

    float* out_f   = (float*)d_out;
    float* tok_out = out_f;
    float* log_out = with_tok ? (out_f + (size_t)BB * L) : out_f;

    k_pe<<<SMAX, DD>>>();
    k_cavec<<<NLL * BB, 256>>>(memory, ca_in_w, ca_in_b, ca_out_w, ca_out_b);

    for (int t = 0; t < L; t++) {
        for (int l = 0; l < NLL; l++) {
            k_qkv <<<96, 256>>>(embedding, sa_in_w, sa_in_b, l, t);
            k_attn<<<BB, 256>>>(l, t);
            k_proj<<<64, 256>>>(sa_out_w, sa_out_b, l);
            k_ffn1<<<64, 256>>>(ff1_w, ff1_b, ln1_g, ln1_b, ln2_g, ln2_b, l);
            k_ffn2<<<64, 256>>>(ff2_w, ff2_b, l);
            k_ln3 <<<BB, 256>>>(ln3_g, ln3_b, l);
        }
        k_logits<<<148, 256>>>(out_w, out_b, log_out, t, L);
        k_next  <<<1, 32>>>(tok_out, t, L, with_tok);
    }
}

// round 8
// speedup vs baseline: 2.8797x; 2.8524x over previous
#include <cuda_runtime.h>
#include <math.h>

#define BB 8
#define DD 512
#define NHH 8
#define HDD 64
#define HH 2048
#define NLL 2
#define VV 32000
#define SMAX 64
#define EPSL 1e-5f
#define NB 148
#define NT 256
#define GWN (NB*8)

typedef unsigned long long ull;

__device__ float g_pe[SMAX*DD];
__device__ float g_x[BB*DD];
__device__ float g_x2[BB*DD];
__device__ float g_q[BB*DD];
__device__ float g_att[BB*DD];
__device__ float g_proj[BB*DD];
__device__ float g_hbuf[BB*HH];
__device__ float g_f2[BB*DD];
__device__ float g_kc[NLL*BB*NHH*SMAX*HDD];
__device__ float g_vc[NLL*BB*NHH*SMAX*HDD];
__device__ float g_cavec[NLL*BB*DD];
__device__ int   g_tok[BB*SMAX];
__device__ ull   g_amax[BB];
__device__ unsigned g_cnt, g_gen;

__device__ __forceinline__ float wred(float v) {
    v += __shfl_xor_sync(0xffffffffu, v, 16);
    v += __shfl_xor_sync(0xffffffffu, v, 8);
    v += __shfl_xor_sync(0xffffffffu, v, 4);
    v += __shfl_xor_sync(0xffffffffu, v, 2);
    v += __shfl_xor_sync(0xffffffffu, v, 1);
    return v;
}

// grid barrier: per-thread gpu-scope fence (CCTL.IVALL flushes L1D) + count/flag
__device__ __forceinline__ void gsync() {
    __threadfence();
    __syncthreads();
    if (threadIdx.x == 0) {
        volatile unsigned* vg = &g_gen;
        unsigned gen = *vg;
        if (atomicAdd(&g_cnt, 1u) == NB - 1) {
            g_cnt = 0;
            __threadfence();
            *vg = gen + 1;
        } else {
            while (*vg == gen) { }
        }
    }
    __syncthreads();
}

__device__ __forceinline__ ull ffma2(ull a, ull b, ull c) {
    ull d;
    asm("fma.rn.f32x2 %0, %1, %2, %3;" : "=l"(d) : "l"(a), "l"(b), "l"(c));
    return d;
}
__device__ __forceinline__ float f2sum(ull a) {
    return __uint_as_float((unsigned)a) + __uint_as_float((unsigned)(a >> 32));
}

// LN in place on y[4] (float4 per lane, 512 elems across warp)
__device__ __forceinline__ void lnorm(float4* y, const float* gam, const float* bet, int lane) {
    float s = 0.f;
    #pragma unroll
    for (int k = 0; k < 4; k++) s += y[k].x + y[k].y + y[k].z + y[k].w;
    float m = wred(s) * (1.f / DD);
    float v = 0.f;
    #pragma unroll
    for (int k = 0; k < 4; k++) {
        float a = y[k].x - m, b = y[k].y - m, c = y[k].z - m, d = y[k].w - m;
        v += a * a + b * b + c * c + d * d;
    }
    v = wred(v) * (1.f / DD);
    float r = 1.f / sqrtf(v + EPSL);
    #pragma unroll
    for (int k = 0; k < 4; k++) {
        float4 g = ((const float4*)gam)[lane + 32 * k];
        float4 b4 = ((const float4*)bet)[lane + 32 * k];
        y[k].x = (y[k].x - m) * r * g.x + b4.x;
        y[k].y = (y[k].y - m) * r * g.y + b4.y;
        y[k].z = (y[k].z - m) * r * g.z + b4.z;
        y[k].w = (y[k].w - m) * r * g.w + b4.w;
    }
}

__device__ __forceinline__ void dot8(const float* __restrict__ w, const float* xs,
                                     int lane, float* acc) {
    const float4* w4 = (const float4*)w;
    const float4* x4 = (const float4*)xs;
    #pragma unroll
    for (int k = 0; k < 4; k++) {
        float4 ww = w4[lane + 32 * k];
        #pragma unroll
        for (int b = 0; b < 8; b++) {
            float4 h = x4[b * 128 + lane + 32 * k];
            acc[b] += ww.x * h.x + ww.y * h.y + ww.z * h.z + ww.w * h.w;
        }
    }
}

// butterfly-merge: returns on lane L the full sum of a[L&7]
__device__ __forceinline__ float red8m(float* a, int lane) {
    #pragma unroll
    for (int s = 0; s < 3; s++) {
        int off = 1 << s, n = 8 >> (s + 1);
        #pragma unroll
        for (int i = 0; i < n; i++) {
            float x = (lane & off) ? a[2 * i] : a[2 * i + 1];
            float rc = __shfl_xor_sync(0xffffffffu, x, off);
            a[i] = ((lane & off) ? a[2 * i + 1] : a[2 * i]) + rc;
        }
    }
    float v = a[0];
    v += __shfl_xor_sync(0xffffffffu, v, 8);
    v += __shfl_xor_sync(0xffffffffu, v, 16);
    return v;
}
// returns on lane L the full sum of a[L&3]
__device__ __forceinline__ float red4m(float* a, int lane) {
    #pragma unroll
    for (int s = 0; s < 2; s++) {
        int off = 1 << s, n = 4 >> (s + 1);
        #pragma unroll
        for (int i = 0; i < n; i++) {
            float x = (lane & off) ? a[2 * i] : a[2 * i + 1];
            float rc = __shfl_xor_sync(0xffffffffu, x, off);
            a[i] = ((lane & off) ? a[2 * i + 1] : a[2 * i]) + rc;
        }
    }
    float v = a[0];
    v += __shfl_xor_sync(0xffffffffu, v, 4);
    v += __shfl_xor_sync(0xffffffffu, v, 8);
    v += __shfl_xor_sync(0xffffffffu, v, 16);
    return v;
}

__global__ void __launch_bounds__(NT)
kmain(const float* __restrict__ memory, const float* __restrict__ emb,
      const float* __restrict__ sa_in_w, const float* __restrict__ sa_in_b,
      const float* __restrict__ sa_out_w, const float* __restrict__ sa_out_b,
      const float* __restrict__ ca_in_w, const float* __restrict__ ca_in_b,
      const float* __restrict__ ca_out_w, const float* __restrict__ ca_out_b,
      const float* __restrict__ ff1_w, const float* __restrict__ ff1_b,
      const float* __restrict__ ff2_w, const float* __restrict__ ff2_b,
      const float* __restrict__ ln1_g, const float* __restrict__ ln1_b,
      const float* __restrict__ ln2_g, const float* __restrict__ ln2_b,
      const float* __restrict__ ln3_g, const float* __restrict__ ln3_b,
      const float* __restrict__ out_w, const float* __restrict__ out_b,
      float* __restrict__ tok_out, float* __restrict__ log_out, int L, int wt)
{
    __shared__ __align__(16) float xs[BB * HH / 2];   // 32KB staging
    __shared__ float sp[NHH][SMAX];
    __shared__ ull sbest[BB];
    int tid = threadIdx.x, lane = tid & 31, warp = tid >> 5;
    int bx = blockIdx.x, gw = bx * 8 + warp, gtid = bx * NT + tid;

    // ---- setup: PE, tokens, argmax ----
    for (int i = gtid; i < SMAX * DD; i += NB * NT) {
        int d = i & 511;
        double dv = exp((double)(d & ~1) * (-9.210340371976184 / 512.0));
        float arg = (float)(i >> 9) * (float)dv;
        g_pe[i] = (d & 1) ? cosf(arg) : sinf(arg);
    }
    for (int i = gtid; i < BB * SMAX; i += NB * NT)
        g_tok[i] = ((i & (SMAX - 1)) == 0) ? 1 : 0;
    if (gtid < BB) g_amax[gtid] = 0ull;
    gsync();

    // ---- cross-attn constant (Sk=1 => softmax==1) on blocks 0..15 ----
    if (bx < NLL * BB) {
        int l = bx >> 3, b = bx & 7;
        const float4* m4 = (const float4*)(memory + b * DD);
        for (int j = warp; j < DD; j += 8) {
            const float4* w4 = (const float4*)(ca_in_w + ((size_t)l * 3 * DD + 2 * DD + j) * DD);
            float acc = 0.f;
            #pragma unroll
            for (int k = 0; k < 4; k++) {
                float4 w = w4[lane + 32 * k], x = m4[lane + 32 * k];
                acc += w.x * x.x + w.y * x.y + w.z * x.z + w.w * x.w;
            }
            acc = wred(acc);
            if (lane == 0) xs[j] = acc + ca_in_b[l * 3 * DD + 2 * DD + j];
        }
        __syncthreads();
        for (int j = warp; j < DD; j += 8) {
            const float4* w4 = (const float4*)(ca_out_w + ((size_t)l * DD + j) * DD);
            const float4* v4 = (const float4*)xs;
            float acc = 0.f;
            #pragma unroll
            for (int k = 0; k < 4; k++) {
                float4 w = w4[lane + 32 * k], x = v4[lane + 32 * k];
                acc += w.x * x.x + w.y * x.y + w.z * x.z + w.w * x.w;
            }
            acc = wred(acc);
            if (lane == 0) g_cavec[(l * BB + b) * DD + j] = acc + ca_out_b[l * DD + j];
        }
    }
    gsync();

    for (int t = 0; t < L; t++) {
        for (int l = 0; l < NLL; l++) {
            // ---- QKV (embedding/LN3 fused in) ----
            {
                int b = warp;
                float4 y[4];
                if (l == 0) {
                    int tok = g_tok[b * SMAX + t];
                    const float4* e4 = (const float4*)(emb + (size_t)tok * DD);
                    const float4* p4 = (const float4*)(g_pe + t * DD);
                    #pragma unroll
                    for (int k = 0; k < 4; k++) {
                        float4 e = e4[lane + 32 * k], p = p4[lane + 32 * k];
                        y[k] = make_float4(e.x + p.x, e.y + p.y, e.z + p.z, e.w + p.w);
                    }
                } else {
                    #pragma unroll
                    for (int k = 0; k < 4; k++) {
                        float4 a = ((const float4*)(g_x2 + b * DD))[lane + 32 * k];
                        float4 c = ((const float4*)(g_f2 + b * DD))[lane + 32 * k];
                        y[k] = make_float4(a.x + c.x, a.y + c.y, a.z + c.z, a.w + c.w);
                    }
                    lnorm(y, ln3_g + (l - 1) * DD, ln3_b + (l - 1) * DD, lane);
                }
                #pragma unroll
                for (int k = 0; k < 4; k++) {
                    ((float4*)xs)[b * 128 + lane + 32 * k] = y[k];
                    if (bx == 0) ((float4*)g_x)[b * 128 + lane + 32 * k] = y[k];
                }
                __syncthreads();
                for (int j = gw; j < 3 * DD; j += GWN) {
                    float acc[8] = {0, 0, 0, 0, 0, 0, 0, 0};
                    dot8(sa_in_w + ((size_t)l * 3 * DD + j) * DD, xs, lane, acc);
                    float val = red8m(acc, lane);
                    if (lane < 8) {
                        val += sa_in_b[l * 3 * DD + j];
                        if (j < DD) g_q[lane * DD + j] = val;
                        else if (j < 2 * DD) {
                            int h = (j - DD) >> 6, d = (j - DD) & 63;
                            g_kc[(((l * BB + lane) * NHH + h) * SMAX + t) * HDD + d] = val;
                        } else {
                            int h = (j - 2 * DD) >> 6, d = (j - 2 * DD) & 63;
                            g_vc[(((l * BB + lane) * NHH + h) * SMAX + t) * HDD + d] = val;
                        }
                    }
                }
            }
            gsync();

            // ---- self-attn (blocks 0..7, warp = head) ----
            if (bx < BB) {
                int b = bx, h = warp, n = t + 1;
                const float4* q4 = (const float4*)(g_q + b * DD + h * HDD);
                const float* kb = g_kc + (size_t)(((l * BB + b) * NHH + h) * SMAX) * HDD;
                const float* vb = g_vc + (size_t)(((l * BB + b) * NHH + h) * SMAX) * HDD;
                float s0 = -1e30f, s1 = -1e30f;
                if (lane < n) {
                    const float4* k4 = (const float4*)(kb + (size_t)lane * HDD);
                    float a = 0.f;
                    #pragma unroll
                    for (int k = 0; k < 16; k++) {
                        float4 kk = k4[k], qq = q4[k];
                        a += kk.x * qq.x + kk.y * qq.y + kk.z * qq.z + kk.w * qq.w;
                    }
                    s0 = a * 0.125f;
                }
                if (lane + 32 < n) {
                    const float4* k4 = (const float4*)(kb + (size_t)(lane + 32) * HDD);
                    float a = 0.f;
                    #pragma unroll
                    for (int k = 0; k < 16; k++) {
                        float4 kk = k4[k], qq = q4[k];
                        a += kk.x * qq.x + kk.y * qq.y + kk.z * qq.z + kk.w * qq.w;
                    }
                    s1 = a * 0.125f;
                }
                float m = fmaxf(s0, s1);
                #pragma unroll
                for (int off = 16; off; off >>= 1)
                    m = fmaxf(m, __shfl_xor_sync(0xffffffffu, m, off));
                float p0 = (lane < n) ? expf(s0 - m) : 0.f;
                float p1 = (lane + 32 < n) ? expf(s1 - m) : 0.f;
                float sum = wred(p0 + p1);
                sp[h][lane] = p0;
                sp[h][lane + 32] = p1;
                __syncwarp();
                float o0 = 0.f, o1 = 0.f;
                for (int j = 0; j < n; j++) {
                    float p = sp[h][j];
                    o0 += p * vb[(size_t)j * HDD + lane];
                    o1 += p * vb[(size_t)j * HDD + lane + 32];
                }
                float inv = 1.f / sum;
                g_att[b * DD + h * HDD + lane] = o0 * inv;
                g_att[b * DD + h * HDD + lane + 32] = o1 * inv;
            }
            gsync();

            // ---- attn out proj ----
            {
                for (int i = tid; i < BB * DD / 4; i += NT)
                    ((float4*)xs)[i] = ((const float4*)g_att)[i];
                __syncthreads();
                for (int j = gw; j < DD; j += GWN) {
                    float acc[8] = {0, 0, 0, 0, 0, 0, 0, 0};
                    dot8(sa_out_w + ((size_t)l * DD + j) * DD, xs, lane, acc);
                    float val = red8m(acc, lane);
                    if (lane < 8) g_proj[lane * DD + j] = val + sa_out_b[l * DD + j];
                }
            }
            gsync();

            // ---- LN1 -> +cavec -> LN2 -> FFN1 + relu ----
            {
                int b = warp;
                float4 y[4];
                #pragma unroll
                for (int k = 0; k < 4; k++) {
                    float4 a = ((const float4*)(g_x + b * DD))[lane + 32 * k];
                    float4 c = ((const float4*)(g_proj + b * DD))[lane + 32 * k];
                    y[k] = make_float4(a.x + c.x, a.y + c.y, a.z + c.z, a.w + c.w);
                }
                lnorm(y, ln1_g + l * DD, ln1_b + l * DD, lane);
                #pragma unroll
                for (int k = 0; k < 4; k++) {
                    float4 c = ((const float4*)(g_cavec + (l * BB + b) * DD))[lane + 32 * k];
                    y[k].x += c.x; y[k].y += c.y; y[k].z += c.z; y[k].w += c.w;
                }
                lnorm(y, ln2_g + l * DD, ln2_b + l * DD, lane);
                #pragma unroll
                for (int k = 0; k < 4; k++) {
                    ((float4*)xs)[b * 128 + lane + 32 * k] = y[k];
                    if (bx == 0) ((float4*)g_x2)[b * 128 + lane + 32 * k] = y[k];
                }
                __syncthreads();
                for (int j = gw; j < HH; j += GWN) {
                    float acc[8] = {0, 0, 0, 0, 0, 0, 0, 0};
                    dot8(ff1_w + ((size_t)l * HH + j) * DD, xs, lane, acc);
                    float val = red8m(acc, lane);
                    if (lane < 8)
                        g_hbuf[lane * HH + j] = fmaxf(val + ff1_b[l * HH + j], 0.f);
                }
            }
            gsync();

            // ---- FFN2 (two 4-batch halves staged in smem) ----
            for (int half = 0; half < 2; half++) {
                __syncthreads();
                for (int i = tid; i < 4 * HH / 4; i += NT)
                    ((float4*)xs)[i] = ((const float4*)(g_hbuf + half * 4 * HH))[i];
                __syncthreads();
                for (int j = gw; j < DD; j += GWN) {
                    const float4* w4 = (const float4*)(ff2_w + ((size_t)l * DD + j) * HH);
                    const float4* x4 = (const float4*)xs;
                    float acc[4] = {0, 0, 0, 0};
                    #pragma unroll 4
                    for (int k = 0; k < 16; k++) {
                        float4 w = w4[lane + 32 * k];
                        #pragma unroll
                        for (int b = 0; b < 4; b++) {
                            float4 h = x4[b * 512 + lane + 32 * k];
                            acc[b] += w.x * h.x + w.y * h.y + w.z * h.z + w.w * h.w;
                        }
                    }
                    float val = red4m(acc, lane);
                    if (lane < 4)
                        g_f2[(half * 4 + lane) * DD + j] = val + ff2_b[l * DD + j];
                }
            }
            gsync();
        } // layers

        // ---- logits: LN3 fused, 4 rows/warp, f32x2 FMA, butterfly merge ----
        {
            int b = warp;
            float4 y[4];
            #pragma unroll
            for (int k = 0; k < 4; k++) {
                float4 a = ((const float4*)(g_x2 + b * DD))[lane + 32 * k];
                float4 c = ((const float4*)(g_f2 + b * DD))[lane + 32 * k];
                y[k] = make_float4(a.x + c.x, a.y + c.y, a.z + c.z, a.w + c.w);
            }
            lnorm(y, ln3_g + (NLL - 1) * DD, ln3_b + (NLL - 1) * DD, lane);
            #pragma unroll
            for (int k = 0; k < 4; k++)
                ((float4*)xs)[b * 128 + lane + 32 * k] = y[k];
            if (tid < BB) sbest[tid] = 0ull;
            __syncthreads();

            const ulonglong2* hsu = (const ulonglong2*)xs;
            int myb = lane & 7, myr = lane >> 3;
            ull bestk = 0ull;
            for (int v0 = gw * 4; v0 < VV; v0 += GWN * 4) {
                const ulonglong2* wu = (const ulonglong2*)(out_w + (size_t)v0 * DD);
                ull acc[4][8];
                #pragma unroll
                for (int r = 0; r < 4; r++)
                    #pragma unroll
                    for (int bb = 0; bb < 8; bb++) acc[r][bb] = 0ull;
                #pragma unroll
                for (int k = 0; k < 4; k++) {
                    ulonglong2 h[8];
                    #pragma unroll
                    for (int bb = 0; bb < 8; bb++) h[bb] = hsu[bb * 128 + lane + 32 * k];
                    #pragma unroll
                    for (int r = 0; r < 4; r++) {
                        ulonglong2 w = wu[r * 128 + lane + 32 * k];
                        #pragma unroll
                        for (int bb = 0; bb < 8; bb++) {
                            acc[r][bb] = ffma2(w.x, h[bb].x, acc[r][bb]);
                            acc[r][bb] = ffma2(w.y, h[bb].y, acc[r][bb]);
                        }
                    }
                }
                float a[32];
                #pragma unroll
                for (int r = 0; r < 4; r++)
                    #pragma unroll
                    for (int bb = 0; bb < 8; bb++) a[r * 8 + bb] = f2sum(acc[r][bb]);
                // merge: lane L ends with full sum of a[L]
                #pragma unroll
                for (int s = 0; s < 5; s++) {
                    int off = 1 << s, n = 32 >> (s + 1);
                    #pragma unroll
                    for (int i = 0; i < n; i++) {
                        float x = (lane & off) ? a[2 * i] : a[2 * i + 1];
                        float rc = __shfl_xor_sync(0xffffffffu, x, off);
                        a[i] = ((lane & off) ? a[2 * i + 1] : a[2 * i]) + rc;
                    }
                }
                int v = v0 + myr;
                float val = a[0] + out_b[v];
                log_out[((size_t)myb * L + t) * VV + v] = val;
                unsigned u = __float_as_uint(val);
                u = (u & 0x80000000u) ? ~u : (u | 0x80000000u);
                ull key = ((ull)u << 32) | (unsigned)(0xFFFFFFFFu - (unsigned)v);
                if (key > bestk) bestk = key;
            }
            ull o = __shfl_xor_sync(0xffffffffu, bestk, 8);  if (o > bestk) bestk = o;
            o     = __shfl_xor_sync(0xffffffffu, bestk, 16); if (o > bestk) bestk = o;
            if (myr == 0) atomicMax(&sbest[myb], bestk);
            __syncthreads();
            if (tid < BB) atomicMax(&g_amax[tid], sbest[tid]);
        }
        gsync();

        // ---- token select ----
        if (bx == 0 && tid < BB) {
            ull key = g_amax[tid];
            int idx = (int)(0xFFFFFFFFu - (unsigned)(key & 0xFFFFFFFFull));
            g_tok[tid * SMAX + t + 1] = idx;
            if (wt) tok_out[tid * L + t] = (float)idx;
            g_amax[tid] = 0ull;
        }
        gsync();
    }
}

extern "C" void kernel_launch(void* const* d_in, const int* in_sizes, int n_in,
                              void* d_out, int out_size) {
    (void)in_sizes; (void)n_in;
    int L, wt;
    if (out_size % (BB * (VV + 1)) == 0) { L = out_size / (BB * (VV + 1)); wt = 1; }
    else if (out_size % (BB * VV) == 0)  { L = out_size / (BB * VV);       wt = 0; }
    else                                 { L = 48;                         wt = 1; }
    if (L > SMAX - 1) L = SMAX - 1;
    if (L <= 0) return;

    float* out_f = (float*)d_out;
    float* tok_out = out_f;
    float* log_out = wt ? (out_f + (size_t)BB * L) : out_f;

    kmain<<<NB, NT>>>(
        (const float*)d_in[0],  (const float*)d_in[1],  (const float*)d_in[2],
        (const float*)d_in[3],  (const float*)d_in[4],  (const float*)d_in[5],
        (const float*)d_in[6],  (const float*)d_in[7],  (const float*)d_in[8],
        (const float*)d_in[9],  (const float*)d_in[10], (const float*)d_in[11],
        (const float*)d_in[12], (const float*)d_in[13], (const float*)d_in[14],
        (const float*)d_in[15], (const float*)d_in[16], (const float*)d_in[17],
        (const float*)d_in[18], (const float*)d_in[19], (const float*)d_in[20],
        (const float*)d_in[21], tok_out, log_out, L, wt);
}